// round 15
// baseline (speedup 1.0000x reference)
#include <cuda_runtime.h>
#include <cstdint>

// ---------------- problem constants ----------------
#define NTHREADS 256
#define NB       14          // batch rows per CTA
#define NBT      7           // rows per fused thread (row split)
#define NCTA     148
#define BB       2048
#define TSTEPS   512
#define PP       17
#define HH       50
#define GG       200         // 4*H gates
#define TT       544
#define XW       (TSTEPS*PP)
#define OUTW     (TT*PP)
#define KP       52          // padded hidden stride (floats)
#define XP       20          // padded input stride
#define HSTRIDE  728         // NB*KP, parity buffer stride

// ---------------- smem layout (float offsets) ----------------
// W2/W3 quant-packed, unit-contiguous: [12 chunks][8 quants][50 units][4]
//   + leftover [4 quants][50 units][4] @ +19200. 20000 floats per layer.
// quant content = 16B: {gA k0, gA k1, gB k0, gB k1} (byte-identical to R13).
#define OFF_WU2   0          // 20000
#define OFF_WU3   20000      // 20000
#define OFF_BQ2   40000      // 50*4 (bias per unit, gate-major float4)
#define OFF_BQ3   40200
#define OFF_WLIN  40400      // 17*52 = 884
#define OFF_BLIN  41284      // 17 (+3 pad)
#define OFF_GS1   41304      // 14*200
#define OFF_HS1   44104      // 728
#define OFF_HS2   44832      // 2 x 728 (parity)
#define OFF_HS3   46288      // 2 x 728 (parity)
#define OFF_XS    47744      // 14*20
#define SMEM_FLOATS 48024    // 192,096 bytes

// ---------------- packed f32x2 helpers ----------------
__device__ __forceinline__ void ffma2(uint64_t& d, uint64_t a, uint64_t b) {
    asm("fma.rn.f32x2 %0, %1, %2, %0;" : "+l"(d) : "l"(a), "l"(b));
}
__device__ __forceinline__ uint64_t pack2(float lo, float hi) {
    uint64_t r;
    asm("mov.b64 %0, {%1, %2};" : "=l"(r) : "f"(lo), "f"(hi));
    return r;
}
__device__ __forceinline__ float hadd2(uint64_t v) {
    float lo, hi;
    asm("mov.b64 {%0, %1}, %2;" : "=f"(lo), "=f"(hi) : "l"(v));
    return lo + hi;
}

__device__ __forceinline__ float fsig(float x) {
    return __fdividef(1.0f, 1.0f + __expf(-x));
}
__device__ __forceinline__ float ftanh_(float x) {
    return 2.0f * __fdividef(1.0f, 1.0f + __expf(-2.0f * x)) - 1.0f;
}

extern __shared__ float sm[];

// Fused gates+activation: thread owns unit j (4 gate rows) x 7 rows.
// Weight quants at unit-contiguous addresses; adjacent lanes (pairs) share
// the same address -> broadcast dedup, 2 wavefronts per load.
// Arithmetic bitwise-identical to R13.
__device__ __forceinline__ void layer_fused(
    const float* __restrict__ Wu, const float* __restrict__ Hin,
    const float* __restrict__ Hsame, const float* __restrict__ Bq,
    float* __restrict__ Hdst, float (&c)[NBT], int j, int rbase)
{
    uint64_t ai[NBT], af[NBT], ag[NBT], ao[NBT];
    float4 bq = *(const float4*)(Bq + 4 * j);
#pragma unroll
    for (int r = 0; r < NBT; r++) {
        ai[r] = pack2(bq.x, 0.f);
        af[r] = pack2(bq.y, 0.f);
        ag[r] = pack2(bq.z, 0.f);
        ao[r] = pack2(bq.w, 0.f);
    }

#pragma unroll
    for (int ch = 0; ch < 12; ch++) {
        const float* wq = Wu + ch * 1600 + j * 4;
        ulonglong2 i01a = *(const ulonglong2*)(wq);
        ulonglong2 i23a = *(const ulonglong2*)(wq + 200);
        ulonglong2 i01b = *(const ulonglong2*)(wq + 400);
        ulonglong2 i23b = *(const ulonglong2*)(wq + 600);
        ulonglong2 h01a = *(const ulonglong2*)(wq + 800);
        ulonglong2 h23a = *(const ulonglong2*)(wq + 1000);
        ulonglong2 h01b = *(const ulonglong2*)(wq + 1200);
        ulonglong2 h23b = *(const ulonglong2*)(wq + 1400);
#pragma unroll
        for (int r = 0; r < NBT; r++) {
            ulonglong2 a = *(const ulonglong2*)(Hin   + (rbase + r) * KP + ch * 4);
            ulonglong2 b = *(const ulonglong2*)(Hsame + (rbase + r) * KP + ch * 4);
            ffma2(ai[r], i01a.x, a.x); ffma2(ai[r], i01b.x, a.y);
            ffma2(ai[r], h01a.x, b.x); ffma2(ai[r], h01b.x, b.y);
            ffma2(af[r], i01a.y, a.x); ffma2(af[r], i01b.y, a.y);
            ffma2(af[r], h01a.y, b.x); ffma2(af[r], h01b.y, b.y);
            ffma2(ag[r], i23a.x, a.x); ffma2(ag[r], i23b.x, a.y);
            ffma2(ag[r], h23a.x, b.x); ffma2(ag[r], h23b.x, b.y);
            ffma2(ao[r], i23a.y, a.x); ffma2(ao[r], i23b.y, a.y);
            ffma2(ao[r], h23a.y, b.x); ffma2(ao[r], h23b.y, b.y);
        }
    }
    {   // leftover kpair 24 (k = 48,49)
        const float* wl = Wu + 19200 + j * 4;
        uint64_t i01 = *(const uint64_t*)(wl);
        uint64_t f01 = *(const uint64_t*)(wl + 2);
        ulonglong2 q23 = *(const ulonglong2*)(wl + 200);
        uint64_t h01 = *(const uint64_t*)(wl + 400);
        uint64_t hf1 = *(const uint64_t*)(wl + 402);
        ulonglong2 h23 = *(const ulonglong2*)(wl + 600);
#pragma unroll
        for (int r = 0; r < NBT; r++) {
            uint64_t a = *(const uint64_t*)(Hin   + (rbase + r) * KP + 48);
            uint64_t b = *(const uint64_t*)(Hsame + (rbase + r) * KP + 48);
            ffma2(ai[r], i01, a);   ffma2(ai[r], h01, b);
            ffma2(af[r], f01, a);   ffma2(af[r], hf1, b);
            ffma2(ag[r], q23.x, a); ffma2(ag[r], h23.x, b);
            ffma2(ao[r], q23.y, a); ffma2(ao[r], h23.y, b);
        }
    }
    // fused activation: c stays in registers, h written directly
#pragma unroll
    for (int r = 0; r < NBT; r++) {
        float iv = fsig(hadd2(ai[r]));
        float fv = fsig(hadd2(af[r]));
        float gv = ftanh_(hadd2(ag[r]));
        float ov = fsig(hadd2(ao[r]));
        float cn = fmaf(fv, c[r], iv * gv);
        c[r] = cn;
        Hdst[(rbase + r) * KP + j] = ov * ftanh_(cn);
    }
}

// L1 pointwise: 3 items/thread cover 700 outputs at 256 threads.
__device__ __forceinline__ void act_layer1(
    const float* __restrict__ GS, float* __restrict__ Hdst,
    float (&c)[3], const int (&ar)[3], const int (&aj)[3], const bool (&av)[3])
{
#pragma unroll
    for (int q = 0; q < 3; q++) {
        if (av[q]) {
            int base = ar[q] * GG + aj[q];
            float xi = GS[base];
            float xf = GS[base + HH];
            float xg = GS[base + 2 * HH];
            float xo = GS[base + 3 * HH];
            float iv = fsig(xi), fv = fsig(xf), gv = ftanh_(xg), ov = fsig(xo);
            float cn = fmaf(fv, c[q], iv * gv);
            c[q] = cn;
            Hdst[ar[q] * KP + aj[q]] = ov * ftanh_(cn);
        }
    }
}

__global__ void __launch_bounds__(NTHREADS, 1)
lstm_forward(const float* __restrict__ x,
             const float* __restrict__ Wih1, const float* __restrict__ Whh1,
             const float* __restrict__ bih1, const float* __restrict__ bhh1,
             const float* __restrict__ Wih2, const float* __restrict__ Whh2,
             const float* __restrict__ bih2, const float* __restrict__ bhh2,
             const float* __restrict__ Wih3, const float* __restrict__ Whh3,
             const float* __restrict__ bih3, const float* __restrict__ bhh3,
             const float* __restrict__ Wlin, const float* __restrict__ blin,
             float* __restrict__ out)
{
    const int tid  = threadIdx.x;
    const int row0 = blockIdx.x * NB;

    // L1 gate map: tid in [32,232) -> gate g
    const bool gok = (tid >= 32 && tid < 232);
    const int  g   = gok ? (tid - 32) : 0;
    // Fused map, DENSE on threads 0..199 (warps 0-6):
    //   f<100 -> L2 item f; f>=100 -> L3 item f-100.
    //   item q: unit j = q>>1, row-half rb = (q&1)*7 (adjacent lanes share j).
    const bool fok   = (tid < 200);
    const bool isL2f = (tid < 100);
    const int  fq    = fok ? (isL2f ? tid : tid - 100) : 0;
    const int  jf    = fq >> 1;
    const int  rbf   = (fq & 1) * NBT;
    const int  wuoff = isL2f ? OFF_WU2 : OFF_WU3;
    const int  bqoff = isL2f ? OFF_BQ2 : OFF_BQ3;
    const int  hin_b = isL2f ? OFF_HS1 : OFF_HS2;   // L2 reads HS1 (no parity)
    const int  hsm_b = isL2f ? OFF_HS2 : OFF_HS3;

    // ---- cooperative weight repack: quant layout, unit-contiguous ----
    for (int idx = tid; idx < 20000; idx += NTHREADS) {
        int e = idx & 3;
        int gate, k;
        if (idx < 19200) {
            int ch = idx / 1600;
            int r  = idx - ch * 1600;
            int qt = r / 200;
            int j  = (r - qt * 200) >> 2;
            int half  = qt >> 2;           // 0 = ih, 1 = hh
            int kpsel = (qt >> 1) & 1;
            gate = (qt & 1) * 2 + (e >> 1);
            k    = 2 * (2 * ch + kpsel) + (e & 1);
            int src = (gate * HH + j) * HH + k;
            sm[OFF_WU2 + idx] = half ? Whh2[src] : Wih2[src];
            sm[OFF_WU3 + idx] = half ? Whh3[src] : Wih3[src];
        } else {
            int r  = idx - 19200;
            int qt = r / 200;
            int j  = (r - qt * 200) >> 2;
            int half = qt >> 1;
            gate = (qt & 1) * 2 + (e >> 1);
            k    = 48 + (e & 1);
            int src = (gate * HH + j) * HH + k;
            sm[OFF_WU2 + idx] = half ? Whh2[src] : Wih2[src];
            sm[OFF_WU3 + idx] = half ? Whh3[src] : Wih3[src];
        }
    }
    // biases per unit: float4 {i,f,g,o}
    for (int idx = tid; idx < 200; idx += NTHREADS) {
        int j = idx >> 2, gate = idx & 3;
        int src = gate * HH + j;
        sm[OFF_BQ2 + 4 * j + gate] = bih2[src] + bhh2[src];
        sm[OFF_BQ3 + 4 * j + gate] = bih3[src] + bhh3[src];
    }
    for (int idx = tid; idx < PP * KP; idx += NTHREADS) {
        int p = idx / KP, k = idx - p * KP;
        sm[OFF_WLIN + idx] = (k < HH) ? Wlin[p * HH + k] : 0.f;
    }
    if (tid < PP) sm[OFF_BLIN + tid] = blin[tid];
    // zero HS1 + HS2(x2) + HS3(x2) + XS
    for (int idx = tid; idx < 5 * HSTRIDE; idx += NTHREADS) sm[OFF_HS1 + idx] = 0.f;
    for (int idx = tid; idx < NB * XP; idx += NTHREADS)     sm[OFF_XS  + idx] = 0.f;

    // ---- layer-1 weights in registers as packed k-pairs ----
    uint64_t w1x2[XP / 2];
    uint64_t w1h2[KP / 2];
    float bg1;
    {
#pragma unroll
        for (int i = 0; i < XP / 2; i++) {
            int k0 = 2 * i, k1 = 2 * i + 1;
            float a = (k0 < PP) ? Wih1[g * PP + k0] : 0.f;
            float b = (k1 < PP) ? Wih1[g * PP + k1] : 0.f;
            w1x2[i] = pack2(a, b);
        }
#pragma unroll
        for (int i = 0; i < KP / 2; i++) {
            int k0 = 2 * i, k1 = 2 * i + 1;
            float a = (k0 < HH) ? Whh1[g * HH + k0] : 0.f;
            float b = (k1 < HH) ? Whh1[g * HH + k1] : 0.f;
            w1h2[i] = pack2(a, b);
        }
        bg1 = bih1[g] + bhh1[g];
    }

    // ---- per-thread work-item maps ----
    int ar[3], aj[3]; bool av[3];              // L1 activation items (700)
#pragma unroll
    for (int q = 0; q < 3; q++) {
        int it = tid + q * NTHREADS;
        av[q] = (it < NB * HH);
        int r = it / HH;
        ar[q] = r; aj[q] = it - r * HH;
    }
    const bool hv = (tid < NB * PP);           // head / x-stage item (238)
    const int  hr = hv ? tid / PP : 0;
    const int  hp = hv ? tid - hr * PP : 0;

    float c1[3]   = {0.f, 0.f, 0.f};
    float cF[NBT] = {0.f,0.f,0.f,0.f,0.f,0.f,0.f};

    // ---- stage XS = x(t=0), prefetch xreg = x(t=1) ----
    float xreg = 0.f;
    if (hv) {
        int brow = row0 + hr;
        if (brow < BB) {
            sm[OFF_XS + hr * XP + hp] = x[(size_t)brow * XW + hp];
            xreg = x[(size_t)brow * XW + PP + hp];
        } else {
            sm[OFF_XS + hr * XP + hp] = 0.f;
        }
    }
    __syncthreads();

    // ================= pipelined teacher-forced loop =================
    // iteration i: L1@t=i, L2@t=i-1 (fused), L3@t=i-2 (fused), head@t=i-3
    for (int i = 0; i < TSTEPS + 3; i++) {
        const bool doL1 = (i < TSTEPS);
        const bool doL2 = (i >= 1) && (i < TSTEPS + 1);
        const bool doL3 = (i >= 2) && (i < TSTEPS + 2);
        const bool doHd = (i >= 3);
        const int  th   = i - 3;
        const int  wpar = i & 1;
        const int  rpar = wpar ^ 1;

        // ---------- Phase A ----------
        if (fok && (isL2f ? doL2 : doL3)) {
            const float* Hin   = sm + hin_b + (isL2f ? 0 : rpar * HSTRIDE);
            const float* Hsame = sm + hsm_b + rpar * HSTRIDE;
            float*       Hdst  = sm + hsm_b + wpar * HSTRIDE;
            layer_fused(sm + wuoff, Hin, Hsame, sm + bqoff, Hdst, cF, jf, rbf);
        }
        if (doL1 && gok) {
            uint64_t acc[NB];
#pragma unroll
            for (int r = 0; r < NB; r++) acc[r] = pack2(bg1, 0.f);
#pragma unroll
            for (int c = 0; c < XP / 4; c++) {
#pragma unroll
                for (int r = 0; r < NB; r++) {
                    ulonglong2 v = *(const ulonglong2*)(sm + OFF_XS + r * XP + c * 4);
                    ffma2(acc[r], w1x2[2 * c    ], v.x);
                    ffma2(acc[r], w1x2[2 * c + 1], v.y);
                }
            }
#pragma unroll
            for (int c = 0; c < KP / 4; c++) {
#pragma unroll
                for (int r = 0; r < NB; r++) {
                    ulonglong2 v = *(const ulonglong2*)(sm + OFF_HS1 + r * KP + c * 4);
                    ffma2(acc[r], w1h2[2 * c    ], v.x);
                    ffma2(acc[r], w1h2[2 * c + 1], v.y);
                }
            }
#pragma unroll
            for (int r = 0; r < NB; r++) sm[OFF_GS1 + r * GG + g] = hadd2(acc[r]);
        }
        if (doHd && hv) {
            const float* H3 = sm + OFF_HS3 + rpar * HSTRIDE;
            uint64_t acc = pack2(sm[OFF_BLIN + hp], 0.f);
#pragma unroll
            for (int c = 0; c < KP / 4; c++) {
                ulonglong2 w = *(const ulonglong2*)(sm + OFF_WLIN + hp * KP + c * 4);
                ulonglong2 h = *(const ulonglong2*)(H3 + hr * KP + c * 4);
                ffma2(acc, w.x, h.x);
                ffma2(acc, w.y, h.y);
            }
            float res = hadd2(acc);
            int brow = row0 + hr;
            if (brow < BB) out[(size_t)brow * OUTW + th * PP + hp] = res;
            if (th == TSTEPS - 1) sm[OFF_XS + hr * XP + hp] = res;  // feed tail
        }
        __syncthreads();                       // SA

        // ---------- Phase B: L1 activation + input staging ----------
        if (doL1) act_layer1(sm + OFF_GS1, sm + OFF_HS1, c1, ar, aj, av);
        if (i + 1 < TSTEPS) {
            if (hv) sm[OFF_XS + hr * XP + hp] = xreg;
            if (i + 2 < TSTEPS && hv) {
                int brow = row0 + hr;
                xreg = (brow < BB) ? x[(size_t)brow * XW + (i + 2) * PP + hp] : 0.f;
            }
        }
        __syncthreads();                       // SB
    }

    // ================= sequential autoregressive tail =================
    // h2(511) in HS2[0], h3(511) in HS3[1] (pipeline parity).
    int p2v = 0, p3v = 1;
    for (int t = TSTEPS; t < TT; t++) {
        if (gok) {   // L1 gates
            uint64_t acc[NB];
#pragma unroll
            for (int r = 0; r < NB; r++) acc[r] = pack2(bg1, 0.f);
#pragma unroll
            for (int c = 0; c < XP / 4; c++) {
#pragma unroll
                for (int r = 0; r < NB; r++) {
                    ulonglong2 v = *(const ulonglong2*)(sm + OFF_XS + r * XP + c * 4);
                    ffma2(acc[r], w1x2[2 * c    ], v.x);
                    ffma2(acc[r], w1x2[2 * c + 1], v.y);
                }
            }
#pragma unroll
            for (int c = 0; c < KP / 4; c++) {
#pragma unroll
                for (int r = 0; r < NB; r++) {
                    ulonglong2 v = *(const ulonglong2*)(sm + OFF_HS1 + r * KP + c * 4);
                    ffma2(acc[r], w1h2[2 * c    ], v.x);
                    ffma2(acc[r], w1h2[2 * c + 1], v.y);
                }
            }
#pragma unroll
            for (int r = 0; r < NB; r++) sm[OFF_GS1 + r * GG + g] = hadd2(acc[r]);
        }
        __syncthreads();
        act_layer1(sm + OFF_GS1, sm + OFF_HS1, c1, ar, aj, av);
        __syncthreads();
        if (fok && isL2f)
            layer_fused(sm + OFF_WU2, sm + OFF_HS1,
                        sm + OFF_HS2 + p2v * HSTRIDE, sm + OFF_BQ2,
                        sm + OFF_HS2 + (1 - p2v) * HSTRIDE, cF, jf, rbf);
        __syncthreads();
        if (fok && !isL2f)
            layer_fused(sm + OFF_WU3, sm + OFF_HS2 + (1 - p2v) * HSTRIDE,
                        sm + OFF_HS3 + p3v * HSTRIDE, sm + OFF_BQ3,
                        sm + OFF_HS3 + (1 - p3v) * HSTRIDE, cF, jf, rbf);
        __syncthreads();
        if (hv) {
            const float* H3 = sm + OFF_HS3 + (1 - p3v) * HSTRIDE;
            uint64_t acc = pack2(sm[OFF_BLIN + hp], 0.f);
#pragma unroll
            for (int c = 0; c < KP / 4; c++) {
                ulonglong2 w = *(const ulonglong2*)(sm + OFF_WLIN + hp * KP + c * 4);
                ulonglong2 h = *(const ulonglong2*)(H3 + hr * KP + c * 4);
                ffma2(acc, w.x, h.x);
                ffma2(acc, w.y, h.y);
            }
            float res = hadd2(acc);
            int brow = row0 + hr;
            if (brow < BB) out[(size_t)brow * OUTW + t * PP + hp] = res;
            sm[OFF_XS + hr * XP + hp] = res;   // x(t+1)
        }
        __syncthreads();
        p2v ^= 1; p3v ^= 1;
    }
}

extern "C" void kernel_launch(void* const* d_in, const int* in_sizes, int n_in,
                              void* d_out, int out_size)
{
    const float* x    = (const float*)d_in[0];
    const float* Wih1 = (const float*)d_in[1];
    const float* Whh1 = (const float*)d_in[2];
    const float* bih1 = (const float*)d_in[3];
    const float* bhh1 = (const float*)d_in[4];
    const float* Wih2 = (const float*)d_in[5];
    const float* Whh2 = (const float*)d_in[6];
    const float* bih2 = (const float*)d_in[7];
    const float* bhh2 = (const float*)d_in[8];
    const float* Wih3 = (const float*)d_in[9];
    const float* Whh3 = (const float*)d_in[10];
    const float* bih3 = (const float*)d_in[11];
    const float* bhh3 = (const float*)d_in[12];
    const float* Wlin = (const float*)d_in[13];
    const float* blin = (const float*)d_in[14];
    float* out = (float*)d_out;

    const size_t smem = (size_t)SMEM_FLOATS * sizeof(float);
    cudaFuncSetAttribute(lstm_forward,
                         cudaFuncAttributeMaxDynamicSharedMemorySize, (int)smem);
    lstm_forward<<<NCTA, NTHREADS, smem>>>(
        x, Wih1, Whh1, bih1, bhh1, Wih2, Whh2, bih2, bhh2,
        Wih3, Whh3, bih3, bhh3, Wlin, blin, out);
}

// round 16
// speedup vs baseline: 1.5948x; 1.5948x over previous
#include <cuda_runtime.h>
#include <cstdint>

// ---------------- problem constants ----------------
#define NTHREADS 256
#define NB       14          // batch rows per CTA
#define NBT      7           // rows per fused thread (row split)
#define NCTA     148
#define BB       2048
#define TSTEPS   512
#define PP       17
#define HH       50
#define GG       200         // 4*H gates
#define TT       544
#define XW       (TSTEPS*PP)
#define OUTW     (TT*PP)
#define KP       52          // padded hidden stride (floats)
#define XP       20          // padded input stride
#define HSTRIDE  728         // NB*KP, parity buffer stride

// ---------------- smem layout (float offsets) ----------------
// W2/W3 quant-packed, UNIT-CONTIGUOUS: [12 chunks][8 quants][50 units][4]
//   + leftover [4 quants][50 units][4] @ +19200. 20000 floats per layer.
// quant content = 16B {gA k0, gA k1, gB k0, gB k1} (byte-identical to R13's quants);
// per-lane stride is 16B -> ~4 wavefronts per weight LDS.128 instead of 8.
#define OFF_WU2   0          // 20000
#define OFF_WU3   20000      // 20000
#define OFF_BQ2   40000      // 50*4 (bias per unit, gate-major float4)
#define OFF_BQ3   40200
#define OFF_WLIN  40400      // 17*52 = 884
#define OFF_BLIN  41284      // 17 (+3 pad)
#define OFF_GS1   41304      // 14*200
#define OFF_HS1   44104      // 728
#define OFF_HS2   44832      // 2 x 728 (parity)
#define OFF_HS3   46288      // 2 x 728 (parity)
#define OFF_XS    47744      // 14*20
#define SMEM_FLOATS 48024    // 192,096 bytes

// ---------------- packed f32x2 helpers ----------------
__device__ __forceinline__ void ffma2(uint64_t& d, uint64_t a, uint64_t b) {
    asm("fma.rn.f32x2 %0, %1, %2, %0;" : "+l"(d) : "l"(a), "l"(b));
}
__device__ __forceinline__ uint64_t pack2(float lo, float hi) {
    uint64_t r;
    asm("mov.b64 %0, {%1, %2};" : "=l"(r) : "f"(lo), "f"(hi));
    return r;
}
__device__ __forceinline__ float hadd2(uint64_t v) {
    float lo, hi;
    asm("mov.b64 {%0, %1}, %2;" : "=f"(lo), "=f"(hi) : "l"(v));
    return lo + hi;
}

__device__ __forceinline__ float fsig(float x) {
    return __fdividef(1.0f, 1.0f + __expf(-x));
}
__device__ __forceinline__ float ftanh_(float x) {
    return 2.0f * __fdividef(1.0f, 1.0f + __expf(-2.0f * x)) - 1.0f;
}

extern __shared__ float sm[];

// Fused gates+activation for L2/L3: thread owns unit j (4 gate rows) x 7 rows.
// Weight quants unit-contiguous (16B/lane stride). Arithmetic bitwise-identical
// to the R13 kernel (same per-gate accumulation order).
__device__ __forceinline__ void layer_fused(
    const float* __restrict__ Wu, const float* __restrict__ Hin,
    const float* __restrict__ Hsame, const float* __restrict__ Bq,
    float* __restrict__ Hdst, float (&c)[NBT], int j, int rbase)
{
    uint64_t ai[NBT], af[NBT], ag[NBT], ao[NBT];
    float4 bq = *(const float4*)(Bq + 4 * j);
#pragma unroll
    for (int r = 0; r < NBT; r++) {
        ai[r] = pack2(bq.x, 0.f);
        af[r] = pack2(bq.y, 0.f);
        ag[r] = pack2(bq.z, 0.f);
        ao[r] = pack2(bq.w, 0.f);
    }

#pragma unroll
    for (int ch = 0; ch < 12; ch++) {
        const float* wq = Wu + ch * 1600 + j * 4;
        ulonglong2 i01a = *(const ulonglong2*)(wq);            // ih kp0, gates 0,1
        ulonglong2 i23a = *(const ulonglong2*)(wq + 200);      // ih kp0, gates 2,3
        ulonglong2 i01b = *(const ulonglong2*)(wq + 400);      // ih kp1, gates 0,1
        ulonglong2 i23b = *(const ulonglong2*)(wq + 600);      // ih kp1, gates 2,3
        ulonglong2 h01a = *(const ulonglong2*)(wq + 800);      // hh kp0, gates 0,1
        ulonglong2 h23a = *(const ulonglong2*)(wq + 1000);
        ulonglong2 h01b = *(const ulonglong2*)(wq + 1200);     // hh kp1
        ulonglong2 h23b = *(const ulonglong2*)(wq + 1400);
#pragma unroll
        for (int r = 0; r < NBT; r++) {
            ulonglong2 a = *(const ulonglong2*)(Hin   + (rbase + r) * KP + ch * 4);
            ulonglong2 b = *(const ulonglong2*)(Hsame + (rbase + r) * KP + ch * 4);
            ffma2(ai[r], i01a.x, a.x); ffma2(ai[r], i01b.x, a.y);
            ffma2(ai[r], h01a.x, b.x); ffma2(ai[r], h01b.x, b.y);
            ffma2(af[r], i01a.y, a.x); ffma2(af[r], i01b.y, a.y);
            ffma2(af[r], h01a.y, b.x); ffma2(af[r], h01b.y, b.y);
            ffma2(ag[r], i23a.x, a.x); ffma2(ag[r], i23b.x, a.y);
            ffma2(ag[r], h23a.x, b.x); ffma2(ag[r], h23b.x, b.y);
            ffma2(ao[r], i23a.y, a.x); ffma2(ao[r], i23b.y, a.y);
            ffma2(ao[r], h23a.y, b.x); ffma2(ao[r], h23b.y, b.y);
        }
    }
    {   // leftover kpair 24 (k = 48,49)
        const float* wl = Wu + 19200 + j * 4;
        uint64_t i01 = *(const uint64_t*)(wl);                 // ih gate0
        uint64_t f01 = *(const uint64_t*)(wl + 2);             // ih gate1
        ulonglong2 q23 = *(const ulonglong2*)(wl + 200);       // ih gates 2,3
        uint64_t h01 = *(const uint64_t*)(wl + 400);           // hh gate0
        uint64_t hf1 = *(const uint64_t*)(wl + 402);           // hh gate1
        ulonglong2 h23 = *(const ulonglong2*)(wl + 600);       // hh gates 2,3
#pragma unroll
        for (int r = 0; r < NBT; r++) {
            uint64_t a = *(const uint64_t*)(Hin   + (rbase + r) * KP + 48);
            uint64_t b = *(const uint64_t*)(Hsame + (rbase + r) * KP + 48);
            ffma2(ai[r], i01, a);   ffma2(ai[r], h01, b);
            ffma2(af[r], f01, a);   ffma2(af[r], hf1, b);
            ffma2(ag[r], q23.x, a); ffma2(ag[r], h23.x, b);
            ffma2(ao[r], q23.y, a); ffma2(ao[r], h23.y, b);
        }
    }
    // fused activation: c stays in registers, h written directly
#pragma unroll
    for (int r = 0; r < NBT; r++) {
        float iv = fsig(hadd2(ai[r]));
        float fv = fsig(hadd2(af[r]));
        float gv = ftanh_(hadd2(ag[r]));
        float ov = fsig(hadd2(ao[r]));
        float cn = fmaf(fv, c[r], iv * gv);
        c[r] = cn;
        Hdst[(rbase + r) * KP + j] = ov * ftanh_(cn);
    }
}

// L1 pointwise: 3 items/thread cover 700 outputs at 256 threads.
__device__ __forceinline__ void act_layer1(
    const float* __restrict__ GS, float* __restrict__ Hdst,
    float (&c)[3], const int (&ar)[3], const int (&aj)[3], const bool (&av)[3])
{
#pragma unroll
    for (int q = 0; q < 3; q++) {
        if (av[q]) {
            int base = ar[q] * GG + aj[q];
            float xi = GS[base];
            float xf = GS[base + HH];
            float xg = GS[base + 2 * HH];
            float xo = GS[base + 3 * HH];
            float iv = fsig(xi), fv = fsig(xf), gv = ftanh_(xg), ov = fsig(xo);
            float cn = fmaf(fv, c[q], iv * gv);
            c[q] = cn;
            Hdst[ar[q] * KP + aj[q]] = ov * ftanh_(cn);
        }
    }
}

__global__ void __launch_bounds__(NTHREADS, 1)
lstm_forward(const float* __restrict__ x,
             const float* __restrict__ Wih1, const float* __restrict__ Whh1,
             const float* __restrict__ bih1, const float* __restrict__ bhh1,
             const float* __restrict__ Wih2, const float* __restrict__ Whh2,
             const float* __restrict__ bih2, const float* __restrict__ bhh2,
             const float* __restrict__ Wih3, const float* __restrict__ Whh3,
             const float* __restrict__ bih3, const float* __restrict__ bhh3,
             const float* __restrict__ Wlin, const float* __restrict__ blin,
             float* __restrict__ out)
{
    const int tid  = threadIdx.x;
    const int row0 = blockIdx.x * NB;

    // L1 gate map: tid in [32,232) -> gate g (R13 mapping)
    const bool gok = (tid >= 32 && tid < 232);
    const int  g   = gok ? (tid - 32) : 0;
    // Fused L2: warps 0-3, lanes 0..99. Fused L3: warps 4-7, lanes 128..227. (R13)
    const bool act2 = (tid < 100);
    const int  j2   = (tid < 50) ? tid : (tid - 50);
    const int  rb2  = (tid < 50) ? 0 : NBT;
    const bool act3 = (tid >= 128 && tid < 228);
    const int  t3c  = act3 ? (tid - 128) : 0;
    const int  j3   = (t3c < 50) ? t3c : (t3c - 50);
    const int  rb3  = (t3c < 50) ? 0 : NBT;

    // ---- cooperative weight repack: unit-contiguous quant layout ----
    for (int idx = tid; idx < 20000; idx += NTHREADS) {
        int e = idx & 3;
        int gate, k;
        if (idx < 19200) {
            int ch = idx / 1600;
            int r  = idx - ch * 1600;
            int qt = r / 200;
            int j  = (r - qt * 200) >> 2;
            int half  = qt >> 2;           // 0 = ih, 1 = hh
            int kpsel = (qt >> 1) & 1;
            gate = (qt & 1) * 2 + (e >> 1);
            k    = 2 * (2 * ch + kpsel) + (e & 1);
            int src = (gate * HH + j) * HH + k;
            sm[OFF_WU2 + idx] = half ? Whh2[src] : Wih2[src];
            sm[OFF_WU3 + idx] = half ? Whh3[src] : Wih3[src];
        } else {
            int r  = idx - 19200;
            int qt = r / 200;
            int j  = (r - qt * 200) >> 2;
            int half = qt >> 1;
            gate = (qt & 1) * 2 + (e >> 1);
            k    = 48 + (e & 1);
            int src = (gate * HH + j) * HH + k;
            sm[OFF_WU2 + idx] = half ? Whh2[src] : Wih2[src];
            sm[OFF_WU3 + idx] = half ? Whh3[src] : Wih3[src];
        }
    }
    // biases per unit: float4 {i,f,g,o}
    for (int idx = tid; idx < 200; idx += NTHREADS) {
        int j = idx >> 2, gate = idx & 3;
        int src = gate * HH + j;
        sm[OFF_BQ2 + 4 * j + gate] = bih2[src] + bhh2[src];
        sm[OFF_BQ3 + 4 * j + gate] = bih3[src] + bhh3[src];
    }
    for (int idx = tid; idx < PP * KP; idx += NTHREADS) {
        int p = idx / KP, k = idx - p * KP;
        sm[OFF_WLIN + idx] = (k < HH) ? Wlin[p * HH + k] : 0.f;
    }
    if (tid < PP) sm[OFF_BLIN + tid] = blin[tid];
    // zero HS1 + HS2(x2) + HS3(x2) + XS
    for (int idx = tid; idx < 5 * HSTRIDE; idx += NTHREADS) sm[OFF_HS1 + idx] = 0.f;
    for (int idx = tid; idx < NB * XP; idx += NTHREADS)     sm[OFF_XS  + idx] = 0.f;

    // ---- layer-1 weights in registers as packed k-pairs ----
    uint64_t w1x2[XP / 2];
    uint64_t w1h2[KP / 2];
    float bg1;
    {
#pragma unroll
        for (int i = 0; i < XP / 2; i++) {
            int k0 = 2 * i, k1 = 2 * i + 1;
            float a = (k0 < PP) ? Wih1[g * PP + k0] : 0.f;
            float b = (k1 < PP) ? Wih1[g * PP + k1] : 0.f;
            w1x2[i] = pack2(a, b);
        }
#pragma unroll
        for (int i = 0; i < KP / 2; i++) {
            int k0 = 2 * i, k1 = 2 * i + 1;
            float a = (k0 < HH) ? Whh1[g * HH + k0] : 0.f;
            float b = (k1 < HH) ? Whh1[g * HH + k1] : 0.f;
            w1h2[i] = pack2(a, b);
        }
        bg1 = bih1[g] + bhh1[g];
    }

    // ---- per-thread work-item maps ----
    int ar[3], aj[3]; bool av[3];              // L1 activation items (700)
#pragma unroll
    for (int q = 0; q < 3; q++) {
        int it = tid + q * NTHREADS;
        av[q] = (it < NB * HH);
        int r = it / HH;
        ar[q] = r; aj[q] = it - r * HH;
    }
    const bool hv = (tid < NB * PP);           // head / x-stage item (238)
    const int  hr = hv ? tid / PP : 0;
    const int  hp = hv ? tid - hr * PP : 0;

    float c1[3]   = {0.f, 0.f, 0.f};
    float c2[NBT] = {0.f,0.f,0.f,0.f,0.f,0.f,0.f};
    float c3[NBT] = {0.f,0.f,0.f,0.f,0.f,0.f,0.f};

    // ---- stage XS = x(t=0), prefetch xreg = x(t=1) ----
    float xreg = 0.f;
    if (hv) {
        int brow = row0 + hr;
        if (brow < BB) {
            sm[OFF_XS + hr * XP + hp] = x[(size_t)brow * XW + hp];
            xreg = x[(size_t)brow * XW + PP + hp];
        } else {
            sm[OFF_XS + hr * XP + hp] = 0.f;
        }
    }
    __syncthreads();

    // ================= pipelined teacher-forced loop =================
    // iteration i: L1@t=i, L2@t=i-1 (fused), L3@t=i-2 (fused), head@t=i-3
    for (int i = 0; i < TSTEPS + 3; i++) {
        const bool doL1 = (i < TSTEPS);
        const bool doL2 = (i >= 1) && (i < TSTEPS + 1);
        const bool doL3 = (i >= 2) && (i < TSTEPS + 2);
        const bool doHd = (i >= 3);
        const int  th   = i - 3;
        const int  wpar = i & 1;
        const int  rpar = wpar ^ 1;

        // ---------- Phase A ----------
        if (doL2 && act2)
            layer_fused(sm + OFF_WU2, sm + OFF_HS1,
                        sm + OFF_HS2 + rpar * HSTRIDE, sm + OFF_BQ2,
                        sm + OFF_HS2 + wpar * HSTRIDE, c2, j2, rb2);
        if (doL3 && act3)
            layer_fused(sm + OFF_WU3, sm + OFF_HS2 + rpar * HSTRIDE,
                        sm + OFF_HS3 + rpar * HSTRIDE, sm + OFF_BQ3,
                        sm + OFF_HS3 + wpar * HSTRIDE, c3, j3, rb3);
        if (doL1 && gok) {
            uint64_t acc[NB];
#pragma unroll
            for (int r = 0; r < NB; r++) acc[r] = pack2(bg1, 0.f);
#pragma unroll
            for (int c = 0; c < XP / 4; c++) {
#pragma unroll
                for (int r = 0; r < NB; r++) {
                    ulonglong2 v = *(const ulonglong2*)(sm + OFF_XS + r * XP + c * 4);
                    ffma2(acc[r], w1x2[2 * c    ], v.x);
                    ffma2(acc[r], w1x2[2 * c + 1], v.y);
                }
            }
#pragma unroll
            for (int c = 0; c < KP / 4; c++) {
#pragma unroll
                for (int r = 0; r < NB; r++) {
                    ulonglong2 v = *(const ulonglong2*)(sm + OFF_HS1 + r * KP + c * 4);
                    ffma2(acc[r], w1h2[2 * c    ], v.x);
                    ffma2(acc[r], w1h2[2 * c + 1], v.y);
                }
            }
#pragma unroll
            for (int r = 0; r < NB; r++) sm[OFF_GS1 + r * GG + g] = hadd2(acc[r]);
        }
        if (doHd && hv) {
            const float* H3 = sm + OFF_HS3 + rpar * HSTRIDE;
            uint64_t acc = pack2(sm[OFF_BLIN + hp], 0.f);
#pragma unroll
            for (int c = 0; c < KP / 4; c++) {
                ulonglong2 w = *(const ulonglong2*)(sm + OFF_WLIN + hp * KP + c * 4);
                ulonglong2 h = *(const ulonglong2*)(H3 + hr * KP + c * 4);
                ffma2(acc, w.x, h.x);
                ffma2(acc, w.y, h.y);
            }
            float res = hadd2(acc);
            int brow = row0 + hr;
            if (brow < BB) out[(size_t)brow * OUTW + th * PP + hp] = res;
            if (th == TSTEPS - 1) sm[OFF_XS + hr * XP + hp] = res;  // feed tail
        }
        __syncthreads();                       // SA

        // ---------- Phase B: L1 activation + input staging ----------
        if (doL1) act_layer1(sm + OFF_GS1, sm + OFF_HS1, c1, ar, aj, av);
        if (i + 1 < TSTEPS) {
            if (hv) sm[OFF_XS + hr * XP + hp] = xreg;
            if (i + 2 < TSTEPS && hv) {
                int brow = row0 + hr;
                xreg = (brow < BB) ? x[(size_t)brow * XW + (i + 2) * PP + hp] : 0.f;
            }
        }
        __syncthreads();                       // SB
    }

    // ================= sequential autoregressive tail =================
    // h2(511) in HS2[0], h3(511) in HS3[1] (from pipeline parity).
    int p2v = 0, p3v = 1;
    for (int t = TSTEPS; t < TT; t++) {
        if (gok) {   // L1 gates
            uint64_t acc[NB];
#pragma unroll
            for (int r = 0; r < NB; r++) acc[r] = pack2(bg1, 0.f);
#pragma unroll
            for (int c = 0; c < XP / 4; c++) {
#pragma unroll
                for (int r = 0; r < NB; r++) {
                    ulonglong2 v = *(const ulonglong2*)(sm + OFF_XS + r * XP + c * 4);
                    ffma2(acc[r], w1x2[2 * c    ], v.x);
                    ffma2(acc[r], w1x2[2 * c + 1], v.y);
                }
            }
#pragma unroll
            for (int c = 0; c < KP / 4; c++) {
#pragma unroll
                for (int r = 0; r < NB; r++) {
                    ulonglong2 v = *(const ulonglong2*)(sm + OFF_HS1 + r * KP + c * 4);
                    ffma2(acc[r], w1h2[2 * c    ], v.x);
                    ffma2(acc[r], w1h2[2 * c + 1], v.y);
                }
            }
#pragma unroll
            for (int r = 0; r < NB; r++) sm[OFF_GS1 + r * GG + g] = hadd2(acc[r]);
        }
        __syncthreads();
        act_layer1(sm + OFF_GS1, sm + OFF_HS1, c1, ar, aj, av);
        __syncthreads();
        if (act2)
            layer_fused(sm + OFF_WU2, sm + OFF_HS1,
                        sm + OFF_HS2 + p2v * HSTRIDE, sm + OFF_BQ2,
                        sm + OFF_HS2 + (1 - p2v) * HSTRIDE, c2, j2, rb2);
        __syncthreads();
        if (act3)
            layer_fused(sm + OFF_WU3, sm + OFF_HS2 + (1 - p2v) * HSTRIDE,
                        sm + OFF_HS3 + p3v * HSTRIDE, sm + OFF_BQ3,
                        sm + OFF_HS3 + (1 - p3v) * HSTRIDE, c3, j3, rb3);
        __syncthreads();
        if (hv) {
            const float* H3 = sm + OFF_HS3 + (1 - p3v) * HSTRIDE;
            uint64_t acc = pack2(sm[OFF_BLIN + hp], 0.f);
#pragma unroll
            for (int c = 0; c < KP / 4; c++) {
                ulonglong2 w = *(const ulonglong2*)(sm + OFF_WLIN + hp * KP + c * 4);
                ulonglong2 h = *(const ulonglong2*)(H3 + hr * KP + c * 4);
                ffma2(acc, w.x, h.x);
                ffma2(acc, w.y, h.y);
            }
            float res = hadd2(acc);
            int brow = row0 + hr;
            if (brow < BB) out[(size_t)brow * OUTW + t * PP + hp] = res;
            sm[OFF_XS + hr * XP + hp] = res;   // x(t+1)
        }
        __syncthreads();
        p2v ^= 1; p3v ^= 1;
    }
}

extern "C" void kernel_launch(void* const* d_in, const int* in_sizes, int n_in,
                              void* d_out, int out_size)
{
    const float* x    = (const float*)d_in[0];
    const float* Wih1 = (const float*)d_in[1];
    const float* Whh1 = (const float*)d_in[2];
    const float* bih1 = (const float*)d_in[3];
    const float* bhh1 = (const float*)d_in[4];
    const float* Wih2 = (const float*)d_in[5];
    const float* Whh2 = (const float*)d_in[6];
    const float* bih2 = (const float*)d_in[7];
    const float* bhh2 = (const float*)d_in[8];
    const float* Wih3 = (const float*)d_in[9];
    const float* Whh3 = (const float*)d_in[10];
    const float* bih3 = (const float*)d_in[11];
    const float* bhh3 = (const float*)d_in[12];
    const float* Wlin = (const float*)d_in[13];
    const float* blin = (const float*)d_in[14];
    float* out = (float*)d_out;

    const size_t smem = (size_t)SMEM_FLOATS * sizeof(float);
    cudaFuncSetAttribute(lstm_forward,
                         cudaFuncAttributeMaxDynamicSharedMemorySize, (int)smem);
    lstm_forward<<<NCTA, NTHREADS, smem>>>(
        x, Wih1, Whh1, bih1, bhh1, Wih2, Whh2, bih2, bhh2,
        Wih3, Whh3, bih3, bhh3, Wlin, blin, out);
}